// round 15
// baseline (speedup 1.0000x reference)
#include <cuda_runtime.h>

// ONE-WAVE variant of the converged kernel: 128 blocks x 512 threads.
// Each 512-thread block runs TWO of the original 256-thread tiles (half =
// t>=256) on disjoint 20KB smem regions. Grid 128 < 148 SMs -> every block
// starts in wave 1, eliminating the 2x block serialization of the 256-block
// grid (108 of 148 SMs ran two sequential blocks). Per-thread work, memory
// pattern, and arithmetic are identical to the converged kernel; formerly
// conditional __syncthreads are unconditional (guarded WORK stays
// conditional) so both halves agree on barrier count.
//
// rho' = L rho L^T,  L = A (x) B (x) C  (flat = r*64 + c*4 + j).
// Coupling classes: D {r<4,c<4} (orig blocks 0..15), 16-row classes
// Bc/Cc/Am (orig blocks 16..255). Pairs: D+D (orig 2m,2m+1), generic+generic.

#define RS16 272   // 16-row tiles: 256 cols + 4 pad per 64-col block
#define RSD   80   // 64-row tiles:  64 cols + 4 pad per 16-col block
#define HALFSZ 5120

__device__ __forceinline__ void mix4s(float* p, const int st, const float* M)
{
    float v0 = p[0], v1 = p[st], v2 = p[2*st], v3 = p[3*st];
    p[0]    = M[0] *v0 + M[1] *v1 + M[2] *v2 + M[3] *v3;
    p[st]   = M[4] *v0 + M[5] *v1 + M[6] *v2 + M[7] *v3;
    p[2*st] = M[8] *v0 + M[9] *v1 + M[10]*v2 + M[11]*v3;
    p[3*st] = M[12]*v0 + M[13]*v1 + M[14]*v2 + M[15]*v3;
}

__device__ __forceinline__ void mix4r(float* v, const int st, const float* M)
{
    float v0 = v[0], v1 = v[st], v2 = v[2*st], v3 = v[3*st];
    v[0]    = M[0] *v0 + M[1] *v1 + M[2] *v2 + M[3] *v3;
    v[st]   = M[4] *v0 + M[5] *v1 + M[6] *v2 + M[7] *v3;
    v[2*st] = M[8] *v0 + M[9] *v1 + M[10]*v2 + M[11]*v3;
    v[3*st] = M[12]*v0 + M[13]*v1 + M[14]*v2 + M[15]*v3;
}

__global__ __launch_bounds__(512, 1)
void rbs_fused(const float* __restrict__ in, float* __restrict__ out,
               const float* __restrict__ thetas)
{
    __shared__ float s[2 * HALFSZ];   // 40 KB: one 20KB region per half
    __shared__ float sM[3][16];       // 0:A (row gates), 1:B (col), 2:C (ch)

    const int t512 = threadIdx.x;
    const int half = t512 >> 8;       // 0 or 1
    const int t    = t512 & 255;      // thread id within the half
    const int mb   = blockIdx.x;      // merged block id, [0,128)
    float* sh = &s[half * HALFSZ];

    // ---- build the three 4x4 Givens products ----
    if (t512 < 3) {
        float M[16] = {1,0,0,0, 0,1,0,0, 0,0,1,0, 0,0,0,1};
        const int pi[6] = {0,0,0,1,1,2};
        const int pj[6] = {1,2,3,2,3,3};
#pragma unroll
        for (int g = 0; g < 6; ++g) {
            float th = thetas[t512 * 6 + g];
            float cc = cosf(th), sn = sinf(th);
            int i = pi[g], j = pj[g];
#pragma unroll
            for (int k = 0; k < 4; ++k) {
                float ai = M[i*4 + k], aj = M[j*4 + k];
                M[i*4 + k] =  cc * ai + sn * aj;   // M <- G * M
                M[j*4 + k] = -sn * ai + cc * aj;
            }
        }
#pragma unroll
        for (int k = 0; k < 16; ++k) sM[t512][k] = M[k];
    }

    const float4* in4  = reinterpret_cast<const float4*>(in);
    float4*       out4 = reinterpret_cast<float4*>(out);

    if (mb < 8) {
        // ===== type D: orig blocks b = 2*mb + half  (0..15) ================
        const int b = 2 * mb + half;
        const int ccq = b & 3, chunk = b >> 2;
#pragma unroll
        for (int h = 0; h < 4; ++h) {
            int idx = t + 256*h;
            int l = idx >> 4, c4 = idx & 15;
            int rcl = c4 >> 2, w = c4 & 3;
            int grow = (l >> 4) * 64 + (l & 15);
            int gc4  = (chunk*4 + rcl)*16 + ccq*4 + w;
            float4 v = in4[grow*256 + gc4];
            *reinterpret_cast<float4*>(&sh[l*RSD + rcl*20 + w*4]) = v;
        }
        __syncthreads();
        // row C (j) + row B (cc) fused in registers
        {
            float C4[16], B4[16];
#pragma unroll
            for (int k = 0; k < 16; ++k) { C4[k] = sM[2][k]; B4[k] = sM[1][k]; }
            int rr = t >> 6, q = t & 63;
            int pc = q + 4*(q >> 4);
            float v[16];
#pragma unroll
            for (int k = 0; k < 16; ++k) v[k] = sh[(rr*16 + k)*RSD + pc];
#pragma unroll
            for (int cc = 0; cc < 4; ++cc) mix4r(&v[cc*4], 1, C4);
#pragma unroll
            for (int j = 0; j < 4; ++j)    mix4r(&v[j], 4, B4);
#pragma unroll
            for (int k = 0; k < 16; ++k) sh[(rr*16 + k)*RSD + pc] = v[k];
        }
        __syncthreads();
        // row A across rr (stride 16 rows)
        {
            float A4[16];
#pragma unroll
            for (int k = 0; k < 16; ++k) A4[k] = sM[0][k];
#pragma unroll
            for (int h = 0; h < 4; ++h) {
                int g = t + 256*h;
                int ccj = g >> 6, q = g & 63;
                int pc = q + 4*(q >> 4);
                mix4s(&sh[ccj*RSD + pc], 16*RSD, A4);
            }
        }
        __syncthreads();
        // col C (jc, stride 1)
        {
            float C4[16];
#pragma unroll
            for (int k = 0; k < 16; ++k) C4[k] = sM[2][k];
#pragma unroll
            for (int h = 0; h < 4; ++h) {
                int g = t + 256*h;
                int l = g >> 4, rcl = (g >> 2) & 3, ccl = g & 3;
                mix4s(&sh[l*RSD + rcl*20 + ccl*4], 1, C4);
            }
        }
        __syncthreads();
        // col B (c<4): work only in the ccq==0 quarter; sync unconditional
        if (ccq == 0) {
            float B4[16];
#pragma unroll
            for (int k = 0; k < 16; ++k) B4[k] = sM[1][k];
#pragma unroll
            for (int h = 0; h < 4; ++h) {
                int g = t + 256*h;
                int l = g >> 4, rcl = (g >> 2) & 3, j = g & 3;
                mix4s(&sh[l*RSD + rcl*20 + j], 4, B4);
            }
        }
        __syncthreads();
        // col A (rc<4): work only for chunk 0; sync unconditional
        if (chunk == 0) {
            float A4[16];
#pragma unroll
            for (int k = 0; k < 16; ++k) A4[k] = sM[0][k];
#pragma unroll
            for (int h = 0; h < 4; ++h) {
                int g = t + 256*h;
                int l = g >> 4, ccl = (g >> 2) & 3, j = g & 3;
                mix4s(&sh[l*RSD + ccl*4 + j], 20, A4);
            }
        }
        __syncthreads();
        // store (mirror of load)
#pragma unroll
        for (int h = 0; h < 4; ++h) {
            int idx = t + 256*h;
            int l = idx >> 4, c4 = idx & 15;
            int rcl = c4 >> 2, w = c4 & 3;
            int grow = (l >> 4) * 64 + (l & 15);
            int gc4  = (chunk*4 + rcl)*16 + ccq*4 + w;
            out4[grow*256 + gc4] =
                *reinterpret_cast<float4*>(&sh[l*RSD + rcl*20 + w*4]);
        }
    } else {
        // ===== 16-row classes: orig b = 16 + 2*(mb-8) + half  (16..255) ====
        const int b = 16 + 2 * (mb - 8) + half;
        int typ, chunk, rb_r = 0, rb_c = 0, rb_c0 = 0;
        if (b < 64)       { typ = 0; int id = b - 16;  chunk = id & 3; rb_r = 4 + (id >> 2); }
        else if (b < 112) { typ = 1; int id = b - 64;  chunk = id & 3; rb_c = 4 + (id >> 2); }
        else              { typ = 2; int id = b - 112; chunk = id & 3; int g = id >> 2;
                            rb_r = 4 + g / 3; rb_c0 = 4 + (g % 3) * 4; }
        // load 16 x 256
#pragma unroll
        for (int h = 0; h < 4; ++h) {
            int idx = t + 256*h;
            int l = idx >> 6, c4 = idx & 63;
            int grow = (typ == 0) ? rb_r*64 + l
                     : (typ == 1) ? (l >> 2)*64 + rb_c*4 + (l & 3)
                                  : rb_r*64 + rb_c0*4 + l;
            float4 v = in4[grow*256 + chunk*64 + c4];
            *reinterpret_cast<float4*>(&sh[l*RS16 + (c4 >> 4)*68 + (c4 & 15)*4]) = v;
        }
        __syncthreads();
        // row mixing fully in registers: thread owns one column
        {
            float C4[16], M2[16];
            const float* msrc = (typ == 0) ? sM[1] : sM[0];
#pragma unroll
            for (int k = 0; k < 16; ++k) { C4[k] = sM[2][k]; M2[k] = msrc[k]; }
            int pc = t + 4*(t >> 6);
            float v[16];
#pragma unroll
            for (int k = 0; k < 16; ++k) v[k] = sh[k*RS16 + pc];
#pragma unroll
            for (int qd = 0; qd < 4; ++qd) mix4r(&v[qd*4], 1, C4);   // C on j
            if (typ != 2) {
#pragma unroll
                for (int j = 0; j < 4; ++j) mix4r(&v[j], 4, M2);     // B or A
            }
#pragma unroll
            for (int k = 0; k < 16; ++k) sh[k*RS16 + pc] = v[k];
        }
        __syncthreads();
        // col C (jc): 16 rows x 4 bl x 16 c = 1024 groups
        {
            float C4[16];
#pragma unroll
            for (int k = 0; k < 16; ++k) C4[k] = sM[2][k];
#pragma unroll
            for (int h = 0; h < 4; ++h) {
                int g = t + 256*h;
                int l = g >> 6, bl = (g >> 4) & 3, c = g & 15;
                mix4s(&sh[l*RS16 + bl*68 + c*4], 1, C4);
            }
        }
        __syncthreads();
        // col B (c<4 within each 64-block): 256 groups
        {
            float B4[16];
#pragma unroll
            for (int k = 0; k < 16; ++k) B4[k] = sM[1][k];
            int l = t >> 4, bl = (t >> 2) & 3, j = t & 3;
            mix4s(&sh[l*RS16 + bl*68 + j], 4, B4);
        }
        __syncthreads();
        // col A (rc<4): work only for chunk 0; sync unconditional
        if (chunk == 0) {
            float A4[16];
#pragma unroll
            for (int k = 0; k < 16; ++k) A4[k] = sM[0][k];
#pragma unroll
            for (int h = 0; h < 4; ++h) {
                int g = t + 256*h;
                int l = g >> 6, cc = (g >> 2) & 15, j = g & 3;
                mix4s(&sh[l*RS16 + cc*4 + j], 68, A4);
            }
        }
        __syncthreads();
        // store (mirror of load)
#pragma unroll
        for (int h = 0; h < 4; ++h) {
            int idx = t + 256*h;
            int l = idx >> 6, c4 = idx & 63;
            int grow = (typ == 0) ? rb_r*64 + l
                     : (typ == 1) ? (l >> 2)*64 + rb_c*4 + (l & 3)
                                  : rb_r*64 + rb_c0*4 + l;
            out4[grow*256 + chunk*64 + c4] =
                *reinterpret_cast<float4*>(&sh[l*RS16 + (c4 >> 4)*68 + (c4 & 15)*4]);
        }
    }
}

extern "C" void kernel_launch(void* const* d_in, const int* in_sizes, int n_in,
                              void* d_out, int out_size)
{
    const float* state  = nullptr;
    const float* thetas = nullptr;
    for (int i = 0; i < n_in; ++i) {
        if (in_sizes[i] == 18 && !thetas)
            thetas = (const float*)d_in[i];
        else if (in_sizes[i] == 1024 * 1024 && !state)
            state = (const float*)d_in[i];
    }
    rbs_fused<<<128, 512>>>(state, (float*)d_out, thetas);
}

// round 16
// speedup vs baseline: 1.2137x; 1.2137x over previous
#include <cuda_runtime.h>

// FINAL — converged kernel (best sample 8.70 us; ncu-stable 9.4-9.6 us;
// wall noise ~ +/-0.8 us across 4 runs of this binary; rel_err 1.39e-7).
//
// rho' = L rho L^T,  L = A (x) B (x) C  (flat index = r*64 + c*4 + j,
// r,c in [0,16), j in [0,4)).  A,B are identity outside indices 0..3, so the
// index space splits into independent coupling classes:
//   D : {r<4, c<4}                -> one class of 64 indices
//   Cc: {r<4, c fixed >=4}        -> 12 classes of 16
//   Bc: {r fixed >=4, c<4}        -> 12 classes of 16
//   Am: {r>=4, c>=4}              -> 144 classes of 4 (merged 4-at-a-time)
// out[I,J] = (L|I) rho[I,J] (L|J)^T per class pair, so ONE kernel: each block
// owns a row-class x column range of whole column classes, applies row mixing
// (in registers) and column mixing (in padded smem), reads/writes each element
// exactly once, fully coalesced. No scratch, no second pass, no transpose.
//
// Convergence evidence (all falsified as levers): occupancy 12->38%, syncs
// 6->0, shuffle column mixes, half-column split, block reordering, one-wave
// 128x512 merge. Residual time is latency/clock-regime bound (replay-loop
// kernel never ramps DVFS), not an intra-kernel property.

#define RS16 272   // 16-row tiles: 256 cols + 4 pad per 64-col block
#define RSD   80   // 64-row tiles:  64 cols + 4 pad per 16-col block

__device__ __forceinline__ void mix4s(float* p, const int st, const float* M)
{
    float v0 = p[0], v1 = p[st], v2 = p[2*st], v3 = p[3*st];
    p[0]    = M[0] *v0 + M[1] *v1 + M[2] *v2 + M[3] *v3;
    p[st]   = M[4] *v0 + M[5] *v1 + M[6] *v2 + M[7] *v3;
    p[2*st] = M[8] *v0 + M[9] *v1 + M[10]*v2 + M[11]*v3;
    p[3*st] = M[12]*v0 + M[13]*v1 + M[14]*v2 + M[15]*v3;
}

__device__ __forceinline__ void mix4r(float* v, const int st, const float* M)
{
    float v0 = v[0], v1 = v[st], v2 = v[2*st], v3 = v[3*st];
    v[0]    = M[0] *v0 + M[1] *v1 + M[2] *v2 + M[3] *v3;
    v[st]   = M[4] *v0 + M[5] *v1 + M[6] *v2 + M[7] *v3;
    v[2*st] = M[8] *v0 + M[9] *v1 + M[10]*v2 + M[11]*v3;
    v[3*st] = M[12]*v0 + M[13]*v1 + M[14]*v2 + M[15]*v3;
}

__global__ __launch_bounds__(256)
void rbs_fused(const float* __restrict__ in, float* __restrict__ out,
               const float* __restrict__ thetas)
{
    __shared__ float s[64 * RSD];   // 20480 B; 16*RS16 = 4352 floats also fits
    __shared__ float sM[3][16];     // 0:A (row gates), 1:B (col), 2:C (ch)

    const int t = threadIdx.x;
    const int b = blockIdx.x;

    // ---- build the three 4x4 Givens products ----
    if (t < 3) {
        float M[16] = {1,0,0,0, 0,1,0,0, 0,0,1,0, 0,0,0,1};
        const int pi[6] = {0,0,0,1,1,2};
        const int pj[6] = {1,2,3,2,3,3};
#pragma unroll
        for (int g = 0; g < 6; ++g) {
            float th = thetas[t * 6 + g];
            float cc = cosf(th), sn = sinf(th);
            int i = pi[g], j = pj[g];
#pragma unroll
            for (int k = 0; k < 4; ++k) {
                float ai = M[i*4 + k], aj = M[j*4 + k];
                M[i*4 + k] =  cc * ai + sn * aj;   // M <- G * M
                M[j*4 + k] = -sn * ai + cc * aj;
            }
        }
#pragma unroll
        for (int k = 0; k < 16; ++k) sM[t][k] = M[k];
    }

    const float4* in4  = reinterpret_cast<const float4*>(in);
    float4*       out4 = reinterpret_cast<float4*>(out);

    if (b < 16) {
        // ================= type D: 64 rows {r<4,c<4} x 64 cols =============
        const int ccq = b & 3, chunk = b >> 2;   // c-quarter, rc-chunk
#pragma unroll
        for (int h = 0; h < 4; ++h) {
            int idx = t + 256*h;
            int l = idx >> 4, c4 = idx & 15;
            int rcl = c4 >> 2, w = c4 & 3;
            int grow = (l >> 4) * 64 + (l & 15);
            int gc4  = (chunk*4 + rcl)*16 + ccq*4 + w;
            float4 v = in4[grow*256 + gc4];
            *reinterpret_cast<float4*>(&s[l*RSD + rcl*20 + w*4]) = v;
        }
        __syncthreads();
        // row C (j) + row B (cc) fused in registers: thread owns (rr, col)
        {
            float C4[16], B4[16];
#pragma unroll
            for (int k = 0; k < 16; ++k) { C4[k] = sM[2][k]; B4[k] = sM[1][k]; }
            int rr = t >> 6, q = t & 63;
            int pc = q + 4*(q >> 4);
            float v[16];
#pragma unroll
            for (int k = 0; k < 16; ++k) v[k] = s[(rr*16 + k)*RSD + pc];
#pragma unroll
            for (int cc = 0; cc < 4; ++cc) mix4r(&v[cc*4], 1, C4);
#pragma unroll
            for (int j = 0; j < 4; ++j)    mix4r(&v[j], 4, B4);
#pragma unroll
            for (int k = 0; k < 16; ++k) s[(rr*16 + k)*RSD + pc] = v[k];
        }
        __syncthreads();
        // row A across rr (stride 16 rows)
        {
            float A4[16];
#pragma unroll
            for (int k = 0; k < 16; ++k) A4[k] = sM[0][k];
#pragma unroll
            for (int h = 0; h < 4; ++h) {
                int g = t + 256*h;
                int ccj = g >> 6, q = g & 63;
                int pc = q + 4*(q >> 4);
                mix4s(&s[ccj*RSD + pc], 16*RSD, A4);
            }
        }
        __syncthreads();
        // col C (jc, stride 1): 64 rows x 4 rcl x 4 ccl = 1024 groups
        {
            float C4[16];
#pragma unroll
            for (int k = 0; k < 16; ++k) C4[k] = sM[2][k];
#pragma unroll
            for (int h = 0; h < 4; ++h) {
                int g = t + 256*h;
                int l = g >> 4, rcl = (g >> 2) & 3, ccl = g & 3;
                mix4s(&s[l*RSD + rcl*20 + ccl*4], 1, C4);
            }
        }
        __syncthreads();
        // col B (c<4): only the ccq==0 quarter holds those columns
        if (ccq == 0) {
            float B4[16];
#pragma unroll
            for (int k = 0; k < 16; ++k) B4[k] = sM[1][k];
#pragma unroll
            for (int h = 0; h < 4; ++h) {
                int g = t + 256*h;
                int l = g >> 4, rcl = (g >> 2) & 3, j = g & 3;
                mix4s(&s[l*RSD + rcl*20 + j], 4, B4);
            }
            __syncthreads();
        }
        // col A (rc<4): only chunk 0
        if (chunk == 0) {
            float A4[16];
#pragma unroll
            for (int k = 0; k < 16; ++k) A4[k] = sM[0][k];
#pragma unroll
            for (int h = 0; h < 4; ++h) {
                int g = t + 256*h;
                int l = g >> 4, ccl = (g >> 2) & 3, j = g & 3;
                mix4s(&s[l*RSD + ccl*4 + j], 20, A4);
            }
            __syncthreads();
        }
        // store (mirror of load)
#pragma unroll
        for (int h = 0; h < 4; ++h) {
            int idx = t + 256*h;
            int l = idx >> 4, c4 = idx & 15;
            int rcl = c4 >> 2, w = c4 & 3;
            int grow = (l >> 4) * 64 + (l & 15);
            int gc4  = (chunk*4 + rcl)*16 + ccq*4 + w;
            out4[grow*256 + gc4] =
                *reinterpret_cast<float4*>(&s[l*RSD + rcl*20 + w*4]);
        }
    } else {
        // ============ 16-row classes x 256-col chunk =======================
        int typ, chunk, rb_r = 0, rb_c = 0, rb_c0 = 0;
        if (b < 64)       { typ = 0; int id = b - 16;  chunk = id & 3; rb_r = 4 + (id >> 2); }            // Bc: rows r*64 + l
        else if (b < 112) { typ = 1; int id = b - 64;  chunk = id & 3; rb_c = 4 + (id >> 2); }            // Cc: rows (l>>2)*64 + c*4 + (l&3)
        else              { typ = 2; int id = b - 112; chunk = id & 3; int g = id >> 2;
                            rb_r = 4 + g / 3; rb_c0 = 4 + (g % 3) * 4; }                                  // Am: rows r*64 + c0*4 + l
        // load 16 x 256
#pragma unroll
        for (int h = 0; h < 4; ++h) {
            int idx = t + 256*h;
            int l = idx >> 6, c4 = idx & 63;
            int grow = (typ == 0) ? rb_r*64 + l
                     : (typ == 1) ? (l >> 2)*64 + rb_c*4 + (l & 3)
                                  : rb_r*64 + rb_c0*4 + l;
            float4 v = in4[grow*256 + chunk*64 + c4];
            *reinterpret_cast<float4*>(&s[l*RS16 + (c4 >> 4)*68 + (c4 & 15)*4]) = v;
        }
        __syncthreads();
        // row mixing fully in registers: thread owns one column (16 values)
        {
            float C4[16], M2[16];
            const float* msrc = (typ == 0) ? sM[1] : sM[0];
#pragma unroll
            for (int k = 0; k < 16; ++k) { C4[k] = sM[2][k]; M2[k] = msrc[k]; }
            int pc = t + 4*(t >> 6);
            float v[16];
#pragma unroll
            for (int k = 0; k < 16; ++k) v[k] = s[k*RS16 + pc];
#pragma unroll
            for (int qd = 0; qd < 4; ++qd) mix4r(&v[qd*4], 1, C4);   // C on j
            if (typ != 2) {
#pragma unroll
                for (int j = 0; j < 4; ++j) mix4r(&v[j], 4, M2);     // B or A
            }
#pragma unroll
            for (int k = 0; k < 16; ++k) s[k*RS16 + pc] = v[k];
        }
        __syncthreads();
        // col C (jc): ALL 16 rows x 4 bl x 16 c = 1024 groups
        {
            float C4[16];
#pragma unroll
            for (int k = 0; k < 16; ++k) C4[k] = sM[2][k];
#pragma unroll
            for (int h = 0; h < 4; ++h) {
                int g = t + 256*h;
                int l = g >> 6, bl = (g >> 4) & 3, c = g & 15;
                mix4s(&s[l*RS16 + bl*68 + c*4], 1, C4);
            }
        }
        __syncthreads();
        // col B (c<4 within each 64-block): 16 x 4 x 4 = 256 groups
        {
            float B4[16];
#pragma unroll
            for (int k = 0; k < 16; ++k) B4[k] = sM[1][k];
            int l = t >> 4, bl = (t >> 2) & 3, j = t & 3;
            mix4s(&s[l*RS16 + bl*68 + j], 4, B4);
        }
        __syncthreads();
        // col A (rc<4): only chunk 0
        if (chunk == 0) {
            float A4[16];
#pragma unroll
            for (int k = 0; k < 16; ++k) A4[k] = sM[0][k];
#pragma unroll
            for (int h = 0; h < 4; ++h) {
                int g = t + 256*h;
                int l = g >> 6, cc = (g >> 2) & 15, j = g & 3;
                mix4s(&s[l*RS16 + cc*4 + j], 68, A4);
            }
            __syncthreads();
        }
        // store (mirror of load)
#pragma unroll
        for (int h = 0; h < 4; ++h) {
            int idx = t + 256*h;
            int l = idx >> 6, c4 = idx & 63;
            int grow = (typ == 0) ? rb_r*64 + l
                     : (typ == 1) ? (l >> 2)*64 + rb_c*4 + (l & 3)
                                  : rb_r*64 + rb_c0*4 + l;
            out4[grow*256 + chunk*64 + c4] =
                *reinterpret_cast<float4*>(&s[l*RS16 + (c4 >> 4)*68 + (c4 & 15)*4]);
        }
    }
}

extern "C" void kernel_launch(void* const* d_in, const int* in_sizes, int n_in,
                              void* d_out, int out_size)
{
    const float* state  = nullptr;
    const float* thetas = nullptr;
    for (int i = 0; i < n_in; ++i) {
        if (in_sizes[i] == 18 && !thetas)
            thetas = (const float*)d_in[i];
        else if (in_sizes[i] == 1024 * 1024 && !state)
            state = (const float*)d_in[i];
    }
    rbs_fused<<<256, 256>>>(state, (float*)d_out, thetas);
}